// round 14
// baseline (speedup 1.0000x reference)
#include <cuda_runtime.h>
#include <cuda_fp16.h>
#include <math.h>

// Problem constants
// B=16, W=H=32, C=512, HEADS=4, DH=128, N=1024, P=16, HID=2048

// ---------------- scratch (device globals; no allocation allowed) -------------
__device__ half  g_xfh[16384 * 512];         // xf[bn][c]
__device__ half  g_qkvvTh[4 * 8192 * 1024];  // [m][b*4+h][d][n]
__device__ float g_kvpart[8 * 8192 * 16];    // [src*4+ks][bz*128+d][p]
__device__ half  g_attncah[64 * 128 * 128];  // [bz][d][e]
__device__ float g_capart[256 * 128 * 128];  // [bz*4+ks][d][e]
__device__ half  g_xcah[16 * 512 * 1024];    // [b][h*128+d][n]
__device__ half  g_xsah[16 * 512 * 1024];    // [b][n'*512+c'] flat
__device__ half  g_t1h[16 * 2048 * 1024];    // [b][o][n]
__device__ half  g_t2h[16 * 2048 * 1024];    // [b][o][n]
// fp16 weight copies
__device__ half  g_wqf[4096 * 512];          // rows 0..2047 qkvv_w, 2048..4095 fc1_w
__device__ half  g_wfc2[512 * 2048];
__device__ half  g_wout[256 * 512];
__device__ half  g_wout2[256 * 512];
__device__ half  g_wEFh[2 * 128 * 1024];     // [src][p(128, pad)][n]  rows 16..127 = 0

// ---------------- async copy helpers ------------------------------------------
__device__ __forceinline__ void cpa16(unsigned dst, const void* src) {
    asm volatile("cp.async.cg.shared.global [%0], [%1], 16;\n" :: "r"(dst), "l"(src));
}

// ---------------- epilogues (pair interface: j, j+1) ---------------------------
struct EpiH {
    half* C; long csb; int ldc; const float* biasRow;
    __device__ __forceinline__ void operator()(int bz, int i, int j, float v0, float v1) const {
        if (biasRow) { float b = biasRow[i]; v0 += b; v1 += b; }
        *(half2*)&C[(long)bz * csb + (long)i * ldc + j] = __floats2half2_rn(v0, v1);
    }
};
// combined qkvv+fc1 epilogue: rows <2048 -> qkvvT scatter; rows >=2048 -> t1 (+bias)
struct EpiQF {
    half* qT; half* t1; const float* f1b;
    __device__ __forceinline__ void operator()(int b, int i, int j, float v0, float v1) const {
        if (i < 2048) {
            int m = i >> 9, hh = (i >> 7) & 3, d = i & 127;
            *(half2*)&qT[((long)(m * 64 + b * 4 + hh)) * 131072 + (long)d * 1024 + j] =
                __floats2half2_rn(v0, v1);
        } else {
            int r = i - 2048;
            float bb = f1b[r];
            *(half2*)&t1[(long)b * 2097152 + (long)r * 1024 + j] =
                __floats2half2_rn(v0 + bb, v1 + bb);
        }
    }
};
// kv partial: z = src*4+ks, i = bz*128+d, j = p (<16 valid), fp32 partial
struct EpiKVP {
    float* part;   // [8][8192][16]
    __device__ __forceinline__ void operator()(int z, int i, int j, float v0, float v1) const {
        if (j >= 16) return;
        long idx = ((long)z * 8192 + i) * 16 + j;
        part[idx] = v0; part[idx + 1] = v1;
    }
};
// channel-attn partial: z = bz*4+ks, fp32 partial [256][128][128]
struct EpiCAP {
    float* part;
    __device__ __forceinline__ void operator()(int z, int i, int j, float v0, float v1) const {
        long idx = ((long)z * 128 + i) * 128 + j;
        part[idx] = v0; part[idx + 1] = v1;
    }
};
// final d_out (B,W,H,C) fp32, n -> (h=n>>5, w=n&31), col offset, opt accumulate
struct EpiOut {
    float* out; const float* bias; int coff; int accum;
    __device__ __forceinline__ void operator()(int b, int n, int j, float v0, float v1) const {
        v0 += bias[j]; v1 += bias[j + 1];
        int h = n >> 5, w = n & 31;
        long idx = (((long)(b * 32 + w)) * 32 + h) * 512 + coff + j;
        if (accum) { out[idx] += v0; out[idx + 1] += v1; }
        else       { out[idx] = v0;  out[idx + 1] = v1; }
    }
};

// ---------------- FP16 GEMM: 3-stage cp.async ring, 1 sync/K-step --------------
// C[i][j] = sum_k A(i,k)*B(j,k), fp32 accumulate.
// AT=false: A (M,K) k-contiguous -> smem [m][k] pitch 40, ldmatrix
// AT=true : A (K,M) m-contiguous -> smem [k][m] pitch 136, ldmatrix.trans
// BT analogous. KSPLIT: blockIdx.z = bz*KSPLIT + ks; K = split length.
template<bool AT, bool BT, int KSPLIT, class Epi>
__global__ void __launch_bounds__(256, 2) gemmH(
    const half* __restrict__ A, const half* __restrict__ B,
    int M, int N, int K, int lda, int ldb, long asb, long bsb, Epi epi)
{
    constexpr int ATILE = AT ? 32 * 136 : 128 * 40;   // halves per stage
    constexpr int BTILE = BT ? 128 * 40 : 32 * 136;
    extern __shared__ __align__(16) half sm[];

    int z = blockIdx.z;
    int bz = z / KSPLIT, ks = z % KSPLIT;
    const half* Ab = A + (long)bz * asb + (AT ? (long)ks * K * lda : (long)ks * K);
    const half* Bb = B + (long)bz * bsb + (BT ? (long)ks * K : (long)ks * K * ldb);
    int bm = blockIdx.y * 128, bn = blockIdx.x * 128;
    int tid = threadIdx.x, lane = tid & 31, warp = tid >> 5;
    int wm = (warp >> 2) * 64, wn = (warp & 3) * 32;
    int g = lane >> 2, t = lane & 3;

    unsigned AsU = (unsigned)__cvta_generic_to_shared(sm);
    unsigned BsU = (unsigned)__cvta_generic_to_shared(sm + 3 * ATILE);

    float c[4][4][4];
#pragma unroll
    for (int mt = 0; mt < 4; mt++)
#pragma unroll
        for (int nt = 0; nt < 4; nt++)
#pragma unroll
            for (int r = 0; r < 4; r++) c[mt][nt][r] = 0.f;

    auto issue = [&](int stage, int k0) {
#pragma unroll
        for (int i = 0; i < 2; i++) {
            int item = tid + i * 256;
            if (!AT) {
                int row = item >> 2, cc = item & 3;
                cpa16(AsU + (stage * ATILE + row * 40 + cc * 8) * 2,
                      Ab + (long)(bm + row) * lda + k0 + cc * 8);
            } else {
                int k = item >> 4, cc = item & 15;
                cpa16(AsU + (stage * ATILE + k * 136 + cc * 8) * 2,
                      Ab + (long)(k0 + k) * lda + bm + cc * 8);
            }
        }
#pragma unroll
        for (int i = 0; i < 2; i++) {
            int item = tid + i * 256;
            if (BT) {
                int row = item >> 2, cc = item & 3;
                cpa16(BsU + (stage * BTILE + row * 40 + cc * 8) * 2,
                      Bb + (long)(bn + row) * ldb + k0 + cc * 8);
            } else {
                int k = item >> 4, cc = item & 15;
                cpa16(BsU + (stage * BTILE + k * 136 + cc * 8) * 2,
                      Bb + (long)(k0 + k) * ldb + bn + cc * 8);
            }
        }
        asm volatile("cp.async.commit_group;\n" ::: "memory");
    };

    issue(0, 0);
    issue(1, 32);
    int nsteps = K >> 5;

    for (int si = 0; si < nsteps; si++) {
        int stage = si % 3;
        int kn = (si + 2) * 32;
        if (kn < K) {
            asm volatile("cp.async.wait_group 1;\n" ::: "memory");
        } else {
            asm volatile("cp.async.wait_group 0;\n" ::: "memory");
        }
        __syncthreads();
        if (kn < K) issue((si + 2) % 3, kn);

        unsigned abase = AsU + stage * ATILE * 2;
        unsigned bbase = BsU + stage * BTILE * 2;

#pragma unroll
        for (int kc = 0; kc < 2; kc++) {
            int kb = kc * 16;
            unsigned af[4][4], bf[4][2];
            if (!AT) {
#pragma unroll
                for (int mt = 0; mt < 4; mt++) {
                    int row = wm + mt * 16 + (lane & 15);
                    int kof = kb + ((lane >> 4) << 3);
                    unsigned addr = abase + (row * 40 + kof) * 2;
                    asm volatile(
                        "ldmatrix.sync.aligned.m8n8.x4.shared.b16 {%0,%1,%2,%3}, [%4];"
                        : "=r"(af[mt][0]), "=r"(af[mt][1]), "=r"(af[mt][2]), "=r"(af[mt][3])
                        : "r"(addr));
                }
            } else {
#pragma unroll
                for (int mt = 0; mt < 4; mt++) {
                    int row_k = kb + ((lane >> 4) & 1) * 8 + (lane & 7);
                    int col_m = wm + mt * 16 + ((lane >> 3) & 1) * 8;
                    unsigned addr = abase + (row_k * 136 + col_m) * 2;
                    asm volatile(
                        "ldmatrix.sync.aligned.m8n8.x4.trans.shared.b16 {%0,%1,%2,%3}, [%4];"
                        : "=r"(af[mt][0]), "=r"(af[mt][1]), "=r"(af[mt][2]), "=r"(af[mt][3])
                        : "r"(addr));
                }
            }
            if (BT) {
#pragma unroll
                for (int p = 0; p < 2; p++) {
                    int nt = 2 * p + (lane >> 4);
                    int row = wn + nt * 8 + (lane & 7);
                    int kof = kb + (((lane >> 3) & 1) << 3);
                    unsigned addr = bbase + (row * 40 + kof) * 2;
                    asm volatile(
                        "ldmatrix.sync.aligned.m8n8.x4.shared.b16 {%0,%1,%2,%3}, [%4];"
                        : "=r"(bf[2 * p][0]), "=r"(bf[2 * p][1]),
                          "=r"(bf[2 * p + 1][0]), "=r"(bf[2 * p + 1][1])
                        : "r"(addr));
                }
            } else {
#pragma unroll
                for (int p = 0; p < 2; p++) {
                    int row_k = kb + ((lane >> 3) & 1) * 8 + (lane & 7);
                    int col_n = wn + (2 * p + (lane >> 4)) * 8;
                    unsigned addr = bbase + (row_k * 136 + col_n) * 2;
                    asm volatile(
                        "ldmatrix.sync.aligned.m8n8.x4.trans.shared.b16 {%0,%1,%2,%3}, [%4];"
                        : "=r"(bf[2 * p][0]), "=r"(bf[2 * p][1]),
                          "=r"(bf[2 * p + 1][0]), "=r"(bf[2 * p + 1][1])
                        : "r"(addr));
                }
            }
#pragma unroll
            for (int mt = 0; mt < 4; mt++)
#pragma unroll
                for (int nt = 0; nt < 4; nt++) {
                    asm volatile(
                        "mma.sync.aligned.m16n8k16.row.col.f32.f16.f16.f32 "
                        "{%0,%1,%2,%3},{%4,%5,%6,%7},{%8,%9},{%0,%1,%2,%3};\n"
                        : "+f"(c[mt][nt][0]), "+f"(c[mt][nt][1]),
                          "+f"(c[mt][nt][2]), "+f"(c[mt][nt][3])
                        : "r"(af[mt][0]), "r"(af[mt][1]), "r"(af[mt][2]), "r"(af[mt][3]),
                          "r"(bf[nt][0]), "r"(bf[nt][1]));
                }
        }
    }

#pragma unroll
    for (int mt = 0; mt < 4; mt++)
#pragma unroll
        for (int nt = 0; nt < 4; nt++) {
            int i = wm + mt * 16 + g;
            int j = wn + nt * 8 + t * 2;
            epi(z, bm + i,     bn + j, c[mt][nt][0], c[mt][nt][1]);
            epi(z, bm + i + 8, bn + j, c[mt][nt][2], c[mt][nt][3]);
        }
}

// smem bytes per instantiation
template<bool AT, bool BT>
constexpr int gemm_smem() {
    return ((AT ? 32 * 136 : 128 * 40) + (BT ? 128 * 40 : 32 * 136)) * 3 * 2;
}

// ---------------- weight conversion fp32 -> fp16 -------------------------------
// segments (float4 units): wqf: qkvv 262144 + fc1 262144 | wfc2 262144 | wout 32768 | wout2 32768
__global__ void cvt_weights(const float* __restrict__ qw, const float* __restrict__ f1,
                            const float* __restrict__ f2, const float* __restrict__ ow,
                            const float* __restrict__ o2) {
    long i4 = (long)blockIdx.x * 256 + threadIdx.x;   // < 851968
    const float* src; half* dst; long off;
    if (i4 < 262144)      { src = qw; dst = g_wqf;  off = i4; }
    else if (i4 < 524288) { src = f1; dst = g_wqf + 1048576; off = i4 - 262144; }
    else if (i4 < 786432) { src = f2; dst = g_wfc2; off = i4 - 524288; }
    else if (i4 < 819200) { src = ow; dst = g_wout; off = i4 - 786432; }
    else                  { src = o2; dst = g_wout2; off = i4 - 819200; }
    float4 v = *(const float4*)(src + off * 4);
    half2 h0 = __floats2half2_rn(v.x, v.y), h1 = __floats2half2_rn(v.z, v.w);
    uint2 u; u.x = *(unsigned*)&h0; u.y = *(unsigned*)&h1;
    *(uint2*)(dst + off * 4) = u;
}

// ---------------- pad E_w/F_w into fp16 [2][128][1024], rows>=16 zero ----------
__global__ void pad_wEF(const float* __restrict__ E_w, const float* __restrict__ F_w) {
    long i4 = (long)blockIdx.x * 256 + threadIdx.x;   // < 65536 (float4 units)
    int z = (int)(i4 >> 15);
    long rem = i4 & 32767;
    int p = (int)(rem >> 8);
    int n4 = (int)(rem & 255);
    half2 h0, h1;
    if (p < 16) {
        const float* w = (z ? F_w : E_w) + (long)p * 1024 + n4 * 4;
        float4 v = *(const float4*)w;
        h0 = __floats2half2_rn(v.x, v.y); h1 = __floats2half2_rn(v.z, v.w);
    } else {
        h0 = __floats2half2_rn(0.f, 0.f); h1 = h0;
    }
    uint2 u; u.x = *(unsigned*)&h0; u.y = *(unsigned*)&h1;
    *(uint2*)(g_wEFh + i4 * 4) = u;
}

// ---------------- pack: x (B,W,H,C) fp32 -> xf half [bn][c] --------------------
__global__ void pack_xf(const float* __restrict__ x) {
    int blk = blockIdx.x;                  // b*1024 + n
    int b = blk >> 10, n = blk & 1023;
    int h = n >> 5, w = n & 31;
    const float* src = x + (((long)(b * 32 + w)) * 32 + h) * 512;
    half* dst = g_xfh + (long)blk * 512;
    int t = threadIdx.x; // 128
    float4 v = *(const float4*)&src[t * 4];
    half2 h0 = __floats2half2_rn(v.x, v.y), h1 = __floats2half2_rn(v.z, v.w);
    uint2 u; u.x = *(unsigned*)&h0; u.y = *(unsigned*)&h1;
    *(uint2*)&dst[t * 4] = u;
}

// ---------------- L2-normalize q and k rows (fp16 in place, fp32 math) ---------
__global__ void norm_scale() {
    half* row = g_qkvvTh + (long)blockIdx.x * 1024;   // rows 0..16383 = m0,m1
    int t = threadIdx.x; // 256
    half2 h[2];
    *(uint2*)h = *(const uint2*)(row + t * 4);
    float2 a = __half22float2(h[0]), b = __half22float2(h[1]);
    float s = a.x*a.x + a.y*a.y + b.x*b.x + b.y*b.y;
    __shared__ float sd[256];
    sd[t] = s; __syncthreads();
    for (int o = 128; o > 0; o >>= 1) { if (t < o) sd[t] += sd[t + o]; __syncthreads(); }
    float inv = 1.0f / fmaxf(sqrtf(sd[0]), 1e-12f);
    h[0] = __floats2half2_rn(a.x * inv, a.y * inv);
    h[1] = __floats2half2_rn(b.x * inv, b.y * inv);
    *(uint2*)(row + t * 4) = *(uint2*)h;
}

// ---------------- softmax over e (128): sums 4 K-split partials ----------------
__global__ void softmax_ca(const float* __restrict__ temp) {
    int r = blockIdx.x;           // bz*128 + d
    int bz = r >> 7;
    int h = (bz & 3);
    float tv = temp[h];
    int t = threadIdx.x; // 128
    long base = ((long)(bz * 4) * 128 + (r & 127)) * 128 + t;
    float v = g_capart[base] + g_capart[base + 16384] + g_capart[base + 32768] + g_capart[base + 49152];
    v *= tv;
    __shared__ float sd[128];
    sd[t] = v; __syncthreads();
    for (int o = 64; o > 0; o >>= 1) { if (t < o) sd[t] = fmaxf(sd[t], sd[t + o]); __syncthreads(); }
    float mx = sd[0]; __syncthreads();
    float e = expf(v - mx);
    sd[t] = e; __syncthreads();
    for (int o = 64; o > 0; o >>= 1) { if (t < o) sd[t] += sd[t + o]; __syncthreads(); }
    g_attncah[(long)r * 128 + t] = __float2half(e / sd[0]);
}

// ---------------- fused projected spatial attention (sums kv partials) ---------
__global__ void spatial_attn(const float* __restrict__ temp2,
                             const float* __restrict__ E_b, const float* __restrict__ F_b) {
    int bz = blockIdx.y; int b = bz >> 2, h = bz & 3;
    int n = blockIdx.x * 128 + threadIdx.x;
    __shared__ float kps[128][16];
    __shared__ float vps[128][16];
    for (int i = threadIdx.x; i < 2048; i += 128) {
        int d = i >> 4, p = i & 15;
        long base = ((long)(bz * 128 + d)) * 16 + p;
        float kv = E_b[p], vv = F_b[p];
#pragma unroll
        for (int s = 0; s < 4; s++) {
            kv += g_kvpart[(long)s * 131072 + base];
            vv += g_kvpart[(long)(4 + s) * 131072 + base];
        }
        kps[d][p] = kv; vps[d][p] = vv;
    }
    __syncthreads();
    const half* q = g_qkvvTh + (long)bz * 131072 + n; // m=0 (normalized q)
    float lg[16];
#pragma unroll
    for (int p = 0; p < 16; p++) lg[p] = 0.f;
    for (int d = 0; d < 128; d++) {
        float qv = __half2float(q[(long)d * 1024]);
#pragma unroll
        for (int p = 0; p < 16; p++) lg[p] += qv * kps[d][p];
    }
    float tv = temp2[h];
    float mx = -1e30f;
#pragma unroll
    for (int p = 0; p < 16; p++) { lg[p] *= tv; mx = fmaxf(mx, lg[p]); }
    float s = 0.f;
#pragma unroll
    for (int p = 0; p < 16; p++) { lg[p] = expf(lg[p] - mx); s += lg[p]; }
    float inv = 1.0f / s;
#pragma unroll
    for (int p = 0; p < 16; p++) lg[p] *= inv;
    half* ob = g_xsah + (long)b * 524288 + h * 1024 + n;
    for (int cc = 0; cc < 128; cc += 8) {
        float acc[8];
#pragma unroll
        for (int dd = 0; dd < 8; dd++) acc[dd] = 0.f;
#pragma unroll
        for (int p = 0; p < 16; p++) {
            float ap = lg[p];
#pragma unroll
            for (int dd = 0; dd < 8; dd++) acc[dd] += ap * vps[cc + dd][p];
        }
#pragma unroll
        for (int dd = 0; dd < 8; dd++) ob[(long)(cc + dd) * 4096] = __float2half(acc[dd]);
    }
}

// ---------------- depthwise 3x3 (SAME) + exact GELU, fp16 io --------------------
__global__ void dwconv_gelu(const float* __restrict__ w, const float* __restrict__ bias) {
    long bo = blockIdx.x;                 // b*2048 + o
    int och = (int)(bo & 2047);
    const half* img = g_t1h + bo * 1024;
    __shared__ float s[1024];
    int tid = threadIdx.x; // 256
    {
        uint2 u = *(const uint2*)&img[tid * 4];
        float2 a = __half22float2(*(half2*)&u.x), b2 = __half22float2(*(half2*)&u.y);
        s[tid * 4] = a.x; s[tid * 4 + 1] = a.y; s[tid * 4 + 2] = b2.x; s[tid * 4 + 3] = b2.y;
    }
    float wv[9];
#pragma unroll
    for (int k = 0; k < 9; k++) wv[k] = w[och * 9 + k];
    float bb = bias[och];
    __syncthreads();
    half* ob = g_t2h + bo * 1024;
    for (int p = tid; p < 1024; p += 256) {
        int h = p >> 5, ww = p & 31;
        float acc = bb;
#pragma unroll
        for (int i = 0; i < 3; i++) {
            int hh = h + i - 1;
            if (hh < 0 || hh > 31) continue;
#pragma unroll
            for (int j = 0; j < 3; j++) {
                int w2 = ww + j - 1;
                if (w2 < 0 || w2 > 31) continue;
                acc += s[hh * 32 + w2] * wv[i * 3 + j];
            }
        }
        ob[p] = __float2half(0.5f * acc * (1.0f + erff(acc * 0.70710678118654752440f)));
    }
}

// ---------------- launch ------------------------------------------------------
extern "C" void kernel_launch(void* const* d_in, const int* in_sizes, int n_in,
                              void* d_out_v, int out_size) {
    const float* x      = (const float*)d_in[0];
    const float* qkvv_w = (const float*)d_in[1];
    const float* E_w    = (const float*)d_in[2];
    const float* E_b    = (const float*)d_in[3];
    const float* F_w    = (const float*)d_in[4];
    const float* F_b    = (const float*)d_in[5];
    const float* temp   = (const float*)d_in[6];
    const float* temp2  = (const float*)d_in[7];
    const float* out_w  = (const float*)d_in[8];
    const float* out_b  = (const float*)d_in[9];
    const float* out2_w = (const float*)d_in[10];
    const float* out2_b = (const float*)d_in[11];
    const float* fc1_w  = (const float*)d_in[12];
    const float* fc1_b  = (const float*)d_in[13];
    const float* dw_w   = (const float*)d_in[14];
    const float* dw_b   = (const float*)d_in[15];
    const float* fc2_w  = (const float*)d_in[16];
    const float* fc2_b  = (const float*)d_in[17];
    float* dout = (float*)d_out_v;

    half *p_xfh, *p_qkvvTh, *p_attncah, *p_xcah, *p_xsah, *p_t1h, *p_t2h;
    half *p_wqf, *p_wfc2, *p_wout, *p_wout2, *p_wEFh;
    float *p_kvpart, *p_capart;
    cudaGetSymbolAddress((void**)&p_xfh, g_xfh);
    cudaGetSymbolAddress((void**)&p_qkvvTh, g_qkvvTh);
    cudaGetSymbolAddress((void**)&p_attncah, g_attncah);
    cudaGetSymbolAddress((void**)&p_xcah, g_xcah);
    cudaGetSymbolAddress((void**)&p_xsah, g_xsah);
    cudaGetSymbolAddress((void**)&p_t1h, g_t1h);
    cudaGetSymbolAddress((void**)&p_t2h, g_t2h);
    cudaGetSymbolAddress((void**)&p_wqf, g_wqf);
    cudaGetSymbolAddress((void**)&p_wfc2, g_wfc2);
    cudaGetSymbolAddress((void**)&p_wout, g_wout);
    cudaGetSymbolAddress((void**)&p_wout2, g_wout2);
    cudaGetSymbolAddress((void**)&p_wEFh, g_wEFh);
    cudaGetSymbolAddress((void**)&p_kvpart, g_kvpart);
    cudaGetSymbolAddress((void**)&p_capart, g_capart);

    // opt into >48KB dynamic smem + max shared carveout (2 blocks/SM)
    constexpr int S_FT = gemm_smem<false, true>();   // 61440
    constexpr int S_FF = gemm_smem<false, false>();  // 56832
    constexpr int S_TT = gemm_smem<true, true>();    // 56832
    auto setup = [](const void* f, int smem) {
        cudaFuncSetAttribute(f, cudaFuncAttributeMaxDynamicSharedMemorySize, smem);
        cudaFuncSetAttribute(f, cudaFuncAttributePreferredSharedMemoryCarveout, 100);
    };
    setup((const void*)gemmH<false, true, 1, EpiQF>,  S_FT);
    setup((const void*)gemmH<false, true, 4, EpiKVP>, S_FT);
    setup((const void*)gemmH<false, true, 4, EpiCAP>, S_FT);
    setup((const void*)gemmH<false, false, 1, EpiH>,  S_FF);
    setup((const void*)gemmH<true, true, 1, EpiOut>,  S_TT);
    setup((const void*)gemmH<false, true, 1, EpiOut>, S_FT);

    // ---- fork/join streams inside the capture ----
    cudaStream_t s0 = 0;
    cudaStream_t sA, sB;
    cudaStreamCreateWithFlags(&sA, cudaStreamNonBlocking);
    cudaStreamCreateWithFlags(&sB, cudaStreamNonBlocking);
    cudaEvent_t evRoot, evA, evFc2;
    cudaEventCreateWithFlags(&evRoot, cudaEventDisableTiming);
    cudaEventCreateWithFlags(&evA, cudaEventDisableTiming);
    cudaEventCreateWithFlags(&evFc2, cudaEventDisableTiming);

    // ---- shared prologue + combined qkvv/fc1 GEMM on main stream
    cvt_weights<<<3328, 256, 0, s0>>>(qkvv_w, fc1_w, fc2_w, out_w, out2_w);
    pad_wEF<<<256, 256, 0, s0>>>(E_w, F_w);
    pack_xf<<<16384, 128, 0, s0>>>(x);
    {
        // combined [4096,1024] = [wq;wfc1] @ xf_b^T per batch; feeds both branches
        EpiQF e{p_qkvvTh, p_t1h, fc1_b};
        gemmH<false, true, 1, EpiQF><<<dim3(8, 32, 16), 256, S_FT, s0>>>(
            p_wqf, p_xfh, 4096, 1024, 512, 512, 512, 0, 524288, e);
    }

    cudaEventRecord(evRoot, s0);
    cudaStreamWaitEvent(sA, evRoot, 0);
    cudaStreamWaitEvent(sB, evRoot, 0);

    // ======== branch B (stream sB): dwconv -> fc2 (writes d_out, assign) ========
    dwconv_gelu<<<32768, 256, 0, sB>>>(dw_w, dw_b);
    {
        EpiOut e{dout, fc2_b, 0, 0};
        gemmH<true, true, 1, EpiOut><<<dim3(4, 8, 16), 256, S_TT, sB>>>(
            p_t2h, p_wfc2, 1024, 512, 2048, 1024, 2048, 2097152, 0, e);
    }
    cudaEventRecord(evFc2, sB);

    // ======== branch A (stream sA): attention glue ========
    {
        EpiKVP e{p_kvpart};
        gemmH<false, true, 4, EpiKVP><<<dim3(1, 64, 8), 256, S_FT, sA>>>(
            p_qkvvTh + 8388608, p_wEFh, 8192, 128, 256,
            1024, 1024, 2L * 8388608, 131072, e);
    }
    norm_scale<<<16384, 256, 0, sA>>>();
    {
        EpiCAP e{p_capart};
        gemmH<false, true, 4, EpiCAP><<<dim3(1, 1, 256), 256, S_FT, sA>>>(
            p_qkvvTh, p_qkvvTh + 8388608, 128, 128, 256, 1024, 1024, 131072, 131072, e);
    }
    softmax_ca<<<8192, 128, 0, sA>>>(temp);
    {
        EpiH e{p_xcah, 131072, 1024, nullptr};
        gemmH<false, false, 1, EpiH><<<dim3(8, 1, 64), 256, S_FF, sA>>>(
            p_attncah, p_qkvvTh + 2L * 8388608, 128, 1024, 128, 128, 1024, 16384, 131072, e);
    }
    spatial_attn<<<dim3(8, 64), 128, 0, sA>>>(temp2, E_b, F_b);

    // projections on sA; must follow fc2's assign to d_out
    cudaStreamWaitEvent(sA, evFc2, 0);
    {
        EpiOut e{dout, out_b, 0, 1};
        gemmH<false, true, 1, EpiOut><<<dim3(2, 8, 16), 256, S_FT, sA>>>(
            p_xsah, p_wout, 1024, 256, 512, 512, 512, 524288, 0, e);
    }
    {
        EpiOut e{dout, out2_b, 256, 1};
        gemmH<true, true, 1, EpiOut><<<dim3(2, 8, 16), 256, S_TT, sA>>>(
            p_xcah, p_wout2, 1024, 256, 512, 1024, 512, 524288, 0, e);
    }

    // ---- join back into the main stream
    cudaEventRecord(evA, sA);
    cudaStreamWaitEvent(s0, evA, 0);

    cudaEventDestroy(evRoot);
    cudaEventDestroy(evA);
    cudaEventDestroy(evFc2);
    cudaStreamDestroy(sA);
    cudaStreamDestroy(sB);
}

// round 15
// speedup vs baseline: 1.0764x; 1.0764x over previous
#include <cuda_runtime.h>
#include <cuda_fp16.h>
#include <math.h>

// Problem constants
// B=16, W=H=32, C=512, HEADS=4, DH=128, N=1024, P=16, HID=2048

// ---------------- scratch (device globals; no allocation allowed) -------------
__device__ half  g_xfh[16384 * 512];         // xf[bn][c]
__device__ half  g_qkvvTh[4 * 8192 * 1024];  // [m][b*4+h][d][n]
__device__ float g_kvpart[8 * 8192 * 16];    // [src*4+ks][bz*128+d][p]
__device__ half  g_attncah[64 * 128 * 128];  // [bz][d][e]
__device__ float g_capart[256 * 128 * 128];  // [bz*4+ks][d][e]
__device__ half  g_xcah[16 * 512 * 1024];    // [b][h*128+d][n]
__device__ half  g_xsah[16 * 512 * 1024];    // [b][n'*512+c'] flat
__device__ half  g_t1h[16 * 2048 * 1024];    // [b][o][n]
__device__ half  g_t2h[16 * 2048 * 1024];    // [b][o][n]
// fp16 weight copies
__device__ half  g_wq[2048 * 512];
__device__ half  g_wfc1[2048 * 512];
__device__ half  g_wfc2[512 * 2048];
__device__ half  g_wout[256 * 512];
__device__ half  g_wout2[256 * 512];
__device__ half  g_wEFh[2 * 128 * 1024];     // [src][p(128, pad)][n]  rows 16..127 = 0

// ---------------- async copy helpers ------------------------------------------
__device__ __forceinline__ void cpa16(unsigned dst, const void* src) {
    asm volatile("cp.async.cg.shared.global [%0], [%1], 16;\n" :: "r"(dst), "l"(src));
}

// ---------------- epilogues (pair interface: j, j+1) ---------------------------
struct EpiH {
    half* C; long csb; int ldc; const float* biasRow;
    __device__ __forceinline__ void operator()(int bz, int i, int j, float v0, float v1) const {
        if (biasRow) { float b = biasRow[i]; v0 += b; v1 += b; }
        *(half2*)&C[(long)bz * csb + (long)i * ldc + j] = __floats2half2_rn(v0, v1);
    }
};
// qkvv direct-to-transposed: i = weight row (0..2047) -> (m,h,d); j = n
struct EpiQT {
    half* out;
    __device__ __forceinline__ void operator()(int b, int i, int j, float v0, float v1) const {
        int m = i >> 9, hh = (i >> 7) & 3, d = i & 127;
        *(half2*)&out[((long)(m * 64 + b * 4 + hh)) * 131072 + (long)d * 1024 + j] =
            __floats2half2_rn(v0, v1);
    }
};
// kv partial: z = src*4+ks, i = bz*128+d, j = p (<16 valid), fp32 partial
struct EpiKVP {
    float* part;   // [8][8192][16]
    __device__ __forceinline__ void operator()(int z, int i, int j, float v0, float v1) const {
        if (j >= 16) return;
        long idx = ((long)z * 8192 + i) * 16 + j;
        part[idx] = v0; part[idx + 1] = v1;
    }
};
// channel-attn partial: z = bz*4+ks, fp32 partial [256][128][128]
struct EpiCAP {
    float* part;
    __device__ __forceinline__ void operator()(int z, int i, int j, float v0, float v1) const {
        long idx = ((long)z * 128 + i) * 128 + j;
        part[idx] = v0; part[idx + 1] = v1;
    }
};
// final d_out (B,W,H,C) fp32, n -> (h=n>>5, w=n&31), col offset, opt accumulate
struct EpiOut {
    float* out; const float* bias; int coff; int accum;
    __device__ __forceinline__ void operator()(int b, int n, int j, float v0, float v1) const {
        v0 += bias[j]; v1 += bias[j + 1];
        int h = n >> 5, w = n & 31;
        long idx = (((long)(b * 32 + w)) * 32 + h) * 512 + coff + j;
        if (accum) { out[idx] += v0; out[idx + 1] += v1; }
        else       { out[idx] = v0;  out[idx + 1] = v1; }
    }
};

// ---------------- FP16 GEMM: 3-stage cp.async ring, 1 sync/K-step --------------
// C[i][j] = sum_k A(i,k)*B(j,k), fp32 accumulate.
// AT=false: A (M,K) k-contiguous -> smem [m][k] pitch 40, ldmatrix
// AT=true : A (K,M) m-contiguous -> smem [k][m] pitch 136, ldmatrix.trans
// BT analogous. KSPLIT: blockIdx.z = bz*KSPLIT + ks; K = split length.
template<bool AT, bool BT, int KSPLIT, class Epi>
__global__ void __launch_bounds__(256, 2) gemmH(
    const half* __restrict__ A, const half* __restrict__ B,
    int M, int N, int K, int lda, int ldb, long asb, long bsb, Epi epi)
{
    constexpr int ATILE = AT ? 32 * 136 : 128 * 40;   // halves per stage
    constexpr int BTILE = BT ? 128 * 40 : 32 * 136;
    extern __shared__ __align__(16) half sm[];

    int z = blockIdx.z;
    int bz = z / KSPLIT, ks = z % KSPLIT;
    const half* Ab = A + (long)bz * asb + (AT ? (long)ks * K * lda : (long)ks * K);
    const half* Bb = B + (long)bz * bsb + (BT ? (long)ks * K : (long)ks * K * ldb);
    int bm = blockIdx.y * 128, bn = blockIdx.x * 128;
    int tid = threadIdx.x, lane = tid & 31, warp = tid >> 5;
    int wm = (warp >> 2) * 64, wn = (warp & 3) * 32;
    int g = lane >> 2, t = lane & 3;

    unsigned AsU = (unsigned)__cvta_generic_to_shared(sm);
    unsigned BsU = (unsigned)__cvta_generic_to_shared(sm + 3 * ATILE);

    float c[4][4][4];
#pragma unroll
    for (int mt = 0; mt < 4; mt++)
#pragma unroll
        for (int nt = 0; nt < 4; nt++)
#pragma unroll
            for (int r = 0; r < 4; r++) c[mt][nt][r] = 0.f;

    auto issue = [&](int stage, int k0) {
#pragma unroll
        for (int i = 0; i < 2; i++) {
            int item = tid + i * 256;
            if (!AT) {
                int row = item >> 2, cc = item & 3;
                cpa16(AsU + (stage * ATILE + row * 40 + cc * 8) * 2,
                      Ab + (long)(bm + row) * lda + k0 + cc * 8);
            } else {
                int k = item >> 4, cc = item & 15;
                cpa16(AsU + (stage * ATILE + k * 136 + cc * 8) * 2,
                      Ab + (long)(k0 + k) * lda + bm + cc * 8);
            }
        }
#pragma unroll
        for (int i = 0; i < 2; i++) {
            int item = tid + i * 256;
            if (BT) {
                int row = item >> 2, cc = item & 3;
                cpa16(BsU + (stage * BTILE + row * 40 + cc * 8) * 2,
                      Bb + (long)(bn + row) * ldb + k0 + cc * 8);
            } else {
                int k = item >> 4, cc = item & 15;
                cpa16(BsU + (stage * BTILE + k * 136 + cc * 8) * 2,
                      Bb + (long)(k0 + k) * ldb + bn + cc * 8);
            }
        }
        asm volatile("cp.async.commit_group;\n" ::: "memory");
    };

    issue(0, 0);
    issue(1, 32);
    int nsteps = K >> 5;

    for (int si = 0; si < nsteps; si++) {
        int stage = si % 3;
        int kn = (si + 2) * 32;
        if (kn < K) {
            asm volatile("cp.async.wait_group 1;\n" ::: "memory");
        } else {
            asm volatile("cp.async.wait_group 0;\n" ::: "memory");
        }
        __syncthreads();
        if (kn < K) issue((si + 2) % 3, kn);

        unsigned abase = AsU + stage * ATILE * 2;
        unsigned bbase = BsU + stage * BTILE * 2;

#pragma unroll
        for (int kc = 0; kc < 2; kc++) {
            int kb = kc * 16;
            unsigned af[4][4], bf[4][2];
            if (!AT) {
#pragma unroll
                for (int mt = 0; mt < 4; mt++) {
                    int row = wm + mt * 16 + (lane & 15);
                    int kof = kb + ((lane >> 4) << 3);
                    unsigned addr = abase + (row * 40 + kof) * 2;
                    asm volatile(
                        "ldmatrix.sync.aligned.m8n8.x4.shared.b16 {%0,%1,%2,%3}, [%4];"
                        : "=r"(af[mt][0]), "=r"(af[mt][1]), "=r"(af[mt][2]), "=r"(af[mt][3])
                        : "r"(addr));
                }
            } else {
#pragma unroll
                for (int mt = 0; mt < 4; mt++) {
                    int row_k = kb + ((lane >> 4) & 1) * 8 + (lane & 7);
                    int col_m = wm + mt * 16 + ((lane >> 3) & 1) * 8;
                    unsigned addr = abase + (row_k * 136 + col_m) * 2;
                    asm volatile(
                        "ldmatrix.sync.aligned.m8n8.x4.trans.shared.b16 {%0,%1,%2,%3}, [%4];"
                        : "=r"(af[mt][0]), "=r"(af[mt][1]), "=r"(af[mt][2]), "=r"(af[mt][3])
                        : "r"(addr));
                }
            }
            if (BT) {
#pragma unroll
                for (int p = 0; p < 2; p++) {
                    int nt = 2 * p + (lane >> 4);
                    int row = wn + nt * 8 + (lane & 7);
                    int kof = kb + (((lane >> 3) & 1) << 3);
                    unsigned addr = bbase + (row * 40 + kof) * 2;
                    asm volatile(
                        "ldmatrix.sync.aligned.m8n8.x4.shared.b16 {%0,%1,%2,%3}, [%4];"
                        : "=r"(bf[2 * p][0]), "=r"(bf[2 * p][1]),
                          "=r"(bf[2 * p + 1][0]), "=r"(bf[2 * p + 1][1])
                        : "r"(addr));
                }
            } else {
#pragma unroll
                for (int p = 0; p < 2; p++) {
                    int row_k = kb + ((lane >> 3) & 1) * 8 + (lane & 7);
                    int col_n = wn + (2 * p + (lane >> 4)) * 8;
                    unsigned addr = bbase + (row_k * 136 + col_n) * 2;
                    asm volatile(
                        "ldmatrix.sync.aligned.m8n8.x4.trans.shared.b16 {%0,%1,%2,%3}, [%4];"
                        : "=r"(bf[2 * p][0]), "=r"(bf[2 * p][1]),
                          "=r"(bf[2 * p + 1][0]), "=r"(bf[2 * p + 1][1])
                        : "r"(addr));
                }
            }
#pragma unroll
            for (int mt = 0; mt < 4; mt++)
#pragma unroll
                for (int nt = 0; nt < 4; nt++) {
                    asm volatile(
                        "mma.sync.aligned.m16n8k16.row.col.f32.f16.f16.f32 "
                        "{%0,%1,%2,%3},{%4,%5,%6,%7},{%8,%9},{%0,%1,%2,%3};\n"
                        : "+f"(c[mt][nt][0]), "+f"(c[mt][nt][1]),
                          "+f"(c[mt][nt][2]), "+f"(c[mt][nt][3])
                        : "r"(af[mt][0]), "r"(af[mt][1]), "r"(af[mt][2]), "r"(af[mt][3]),
                          "r"(bf[nt][0]), "r"(bf[nt][1]));
                }
        }
    }

#pragma unroll
    for (int mt = 0; mt < 4; mt++)
#pragma unroll
        for (int nt = 0; nt < 4; nt++) {
            int i = wm + mt * 16 + g;
            int j = wn + nt * 8 + t * 2;
            epi(z, bm + i,     bn + j, c[mt][nt][0], c[mt][nt][1]);
            epi(z, bm + i + 8, bn + j, c[mt][nt][2], c[mt][nt][3]);
        }
}

// smem bytes per instantiation
template<bool AT, bool BT>
constexpr int gemm_smem() {
    return ((AT ? 32 * 136 : 128 * 40) + (BT ? 128 * 40 : 32 * 136)) * 3 * 2;
}

// ---------------- weight conversion fp32 -> fp16 -------------------------------
__global__ void cvt_weights(const float* __restrict__ qw, const float* __restrict__ f1,
                            const float* __restrict__ f2, const float* __restrict__ ow,
                            const float* __restrict__ o2) {
    long i4 = (long)blockIdx.x * 256 + threadIdx.x;   // < 851968
    const float* src; half* dst; long off;
    if (i4 < 262144)      { src = qw; dst = g_wq;   off = i4; }
    else if (i4 < 524288) { src = f1; dst = g_wfc1; off = i4 - 262144; }
    else if (i4 < 786432) { src = f2; dst = g_wfc2; off = i4 - 524288; }
    else if (i4 < 819200) { src = ow; dst = g_wout; off = i4 - 786432; }
    else                  { src = o2; dst = g_wout2; off = i4 - 819200; }
    float4 v = *(const float4*)(src + off * 4);
    half2 h0 = __floats2half2_rn(v.x, v.y), h1 = __floats2half2_rn(v.z, v.w);
    uint2 u; u.x = *(unsigned*)&h0; u.y = *(unsigned*)&h1;
    *(uint2*)(dst + off * 4) = u;
}

// ---------------- pad E_w/F_w into fp16 [2][128][1024], rows>=16 zero ----------
__global__ void pad_wEF(const float* __restrict__ E_w, const float* __restrict__ F_w) {
    long i4 = (long)blockIdx.x * 256 + threadIdx.x;   // < 65536 (float4 units)
    int z = (int)(i4 >> 15);
    long rem = i4 & 32767;
    int p = (int)(rem >> 8);
    int n4 = (int)(rem & 255);
    half2 h0, h1;
    if (p < 16) {
        const float* w = (z ? F_w : E_w) + (long)p * 1024 + n4 * 4;
        float4 v = *(const float4*)w;
        h0 = __floats2half2_rn(v.x, v.y); h1 = __floats2half2_rn(v.z, v.w);
    } else {
        h0 = __floats2half2_rn(0.f, 0.f); h1 = h0;
    }
    uint2 u; u.x = *(unsigned*)&h0; u.y = *(unsigned*)&h1;
    *(uint2*)(g_wEFh + i4 * 4) = u;
}

// ---------------- pack: x (B,W,H,C) fp32 -> xf half [bn][c] --------------------
__global__ void pack_xf(const float* __restrict__ x) {
    int blk = blockIdx.x;                  // b*1024 + n
    int b = blk >> 10, n = blk & 1023;
    int h = n >> 5, w = n & 31;
    const float* src = x + (((long)(b * 32 + w)) * 32 + h) * 512;
    half* dst = g_xfh + (long)blk * 512;
    int t = threadIdx.x; // 128
    float4 v = *(const float4*)&src[t * 4];
    half2 h0 = __floats2half2_rn(v.x, v.y), h1 = __floats2half2_rn(v.z, v.w);
    uint2 u; u.x = *(unsigned*)&h0; u.y = *(unsigned*)&h1;
    *(uint2*)&dst[t * 4] = u;
}

// ---------------- L2-normalize q and k rows (fp16 in place, fp32 math) ---------
__global__ void norm_scale() {
    half* row = g_qkvvTh + (long)blockIdx.x * 1024;   // rows 0..16383 = m0,m1
    int t = threadIdx.x; // 256
    half2 h[2];
    *(uint2*)h = *(const uint2*)(row + t * 4);
    float2 a = __half22float2(h[0]), b = __half22float2(h[1]);
    float s = a.x*a.x + a.y*a.y + b.x*b.x + b.y*b.y;
    __shared__ float sd[256];
    sd[t] = s; __syncthreads();
    for (int o = 128; o > 0; o >>= 1) { if (t < o) sd[t] += sd[t + o]; __syncthreads(); }
    float inv = 1.0f / fmaxf(sqrtf(sd[0]), 1e-12f);
    h[0] = __floats2half2_rn(a.x * inv, a.y * inv);
    h[1] = __floats2half2_rn(b.x * inv, b.y * inv);
    *(uint2*)(row + t * 4) = *(uint2*)h;
}

// ---------------- softmax over e (128): sums 4 K-split partials ----------------
__global__ void softmax_ca(const float* __restrict__ temp) {
    int r = blockIdx.x;           // bz*128 + d
    int bz = r >> 7;
    int h = (bz & 3);
    float tv = temp[h];
    int t = threadIdx.x; // 128
    long base = ((long)(bz * 4) * 128 + (r & 127)) * 128 + t;
    float v = g_capart[base] + g_capart[base + 16384] + g_capart[base + 32768] + g_capart[base + 49152];
    v *= tv;
    __shared__ float sd[128];
    sd[t] = v; __syncthreads();
    for (int o = 64; o > 0; o >>= 1) { if (t < o) sd[t] = fmaxf(sd[t], sd[t + o]); __syncthreads(); }
    float mx = sd[0]; __syncthreads();
    float e = expf(v - mx);
    sd[t] = e; __syncthreads();
    for (int o = 64; o > 0; o >>= 1) { if (t < o) sd[t] += sd[t + o]; __syncthreads(); }
    g_attncah[(long)r * 128 + t] = __float2half(e / sd[0]);
}

// ---------------- fused projected spatial attention (sums kv partials) ---------
__global__ void spatial_attn(const float* __restrict__ temp2,
                             const float* __restrict__ E_b, const float* __restrict__ F_b) {
    int bz = blockIdx.y; int b = bz >> 2, h = bz & 3;
    int n = blockIdx.x * 128 + threadIdx.x;
    __shared__ float kps[128][16];
    __shared__ float vps[128][16];
    for (int i = threadIdx.x; i < 2048; i += 128) {
        int d = i >> 4, p = i & 15;
        long base = ((long)(bz * 128 + d)) * 16 + p;
        float kv = E_b[p], vv = F_b[p];
#pragma unroll
        for (int s = 0; s < 4; s++) {
            kv += g_kvpart[(long)s * 131072 + base];
            vv += g_kvpart[(long)(4 + s) * 131072 + base];
        }
        kps[d][p] = kv; vps[d][p] = vv;
    }
    __syncthreads();
    const half* q = g_qkvvTh + (long)bz * 131072 + n; // m=0 (normalized q)
    float lg[16];
#pragma unroll
    for (int p = 0; p < 16; p++) lg[p] = 0.f;
    for (int d = 0; d < 128; d++) {
        float qv = __half2float(q[(long)d * 1024]);
#pragma unroll
        for (int p = 0; p < 16; p++) lg[p] += qv * kps[d][p];
    }
    float tv = temp2[h];
    float mx = -1e30f;
#pragma unroll
    for (int p = 0; p < 16; p++) { lg[p] *= tv; mx = fmaxf(mx, lg[p]); }
    float s = 0.f;
#pragma unroll
    for (int p = 0; p < 16; p++) { lg[p] = expf(lg[p] - mx); s += lg[p]; }
    float inv = 1.0f / s;
#pragma unroll
    for (int p = 0; p < 16; p++) lg[p] *= inv;
    half* ob = g_xsah + (long)b * 524288 + h * 1024 + n;
    for (int cc = 0; cc < 128; cc += 8) {
        float acc[8];
#pragma unroll
        for (int dd = 0; dd < 8; dd++) acc[dd] = 0.f;
#pragma unroll
        for (int p = 0; p < 16; p++) {
            float ap = lg[p];
#pragma unroll
            for (int dd = 0; dd < 8; dd++) acc[dd] += ap * vps[cc + dd][p];
        }
#pragma unroll
        for (int dd = 0; dd < 8; dd++) ob[(long)(cc + dd) * 4096] = __float2half(acc[dd]);
    }
}

// ---------------- depthwise 3x3 (SAME) + exact GELU, fp16 io --------------------
__global__ void dwconv_gelu(const float* __restrict__ w, const float* __restrict__ bias) {
    long bo = blockIdx.x;                 // b*2048 + o
    int och = (int)(bo & 2047);
    const half* img = g_t1h + bo * 1024;
    __shared__ float s[1024];
    int tid = threadIdx.x; // 256
    {
        uint2 u = *(const uint2*)&img[tid * 4];
        float2 a = __half22float2(*(half2*)&u.x), b2 = __half22float2(*(half2*)&u.y);
        s[tid * 4] = a.x; s[tid * 4 + 1] = a.y; s[tid * 4 + 2] = b2.x; s[tid * 4 + 3] = b2.y;
    }
    float wv[9];
#pragma unroll
    for (int k = 0; k < 9; k++) wv[k] = w[och * 9 + k];
    float bb = bias[och];
    __syncthreads();
    half* ob = g_t2h + bo * 1024;
    for (int p = tid; p < 1024; p += 256) {
        int h = p >> 5, ww = p & 31;
        float acc = bb;
#pragma unroll
        for (int i = 0; i < 3; i++) {
            int hh = h + i - 1;
            if (hh < 0 || hh > 31) continue;
#pragma unroll
            for (int j = 0; j < 3; j++) {
                int w2 = ww + j - 1;
                if (w2 < 0 || w2 > 31) continue;
                acc += s[hh * 32 + w2] * wv[i * 3 + j];
            }
        }
        ob[p] = __float2half(0.5f * acc * (1.0f + erff(acc * 0.70710678118654752440f)));
    }
}

// ---------------- launch ------------------------------------------------------
extern "C" void kernel_launch(void* const* d_in, const int* in_sizes, int n_in,
                              void* d_out_v, int out_size) {
    const float* x      = (const float*)d_in[0];
    const float* qkvv_w = (const float*)d_in[1];
    const float* E_w    = (const float*)d_in[2];
    const float* E_b    = (const float*)d_in[3];
    const float* F_w    = (const float*)d_in[4];
    const float* F_b    = (const float*)d_in[5];
    const float* temp   = (const float*)d_in[6];
    const float* temp2  = (const float*)d_in[7];
    const float* out_w  = (const float*)d_in[8];
    const float* out_b  = (const float*)d_in[9];
    const float* out2_w = (const float*)d_in[10];
    const float* out2_b = (const float*)d_in[11];
    const float* fc1_w  = (const float*)d_in[12];
    const float* fc1_b  = (const float*)d_in[13];
    const float* dw_w   = (const float*)d_in[14];
    const float* dw_b   = (const float*)d_in[15];
    const float* fc2_w  = (const float*)d_in[16];
    const float* fc2_b  = (const float*)d_in[17];
    float* dout = (float*)d_out_v;

    half *p_xfh, *p_qkvvTh, *p_attncah, *p_xcah, *p_xsah, *p_t1h, *p_t2h;
    half *p_wq, *p_wfc1, *p_wfc2, *p_wout, *p_wout2, *p_wEFh;
    float *p_kvpart, *p_capart;
    cudaGetSymbolAddress((void**)&p_xfh, g_xfh);
    cudaGetSymbolAddress((void**)&p_qkvvTh, g_qkvvTh);
    cudaGetSymbolAddress((void**)&p_attncah, g_attncah);
    cudaGetSymbolAddress((void**)&p_xcah, g_xcah);
    cudaGetSymbolAddress((void**)&p_xsah, g_xsah);
    cudaGetSymbolAddress((void**)&p_t1h, g_t1h);
    cudaGetSymbolAddress((void**)&p_t2h, g_t2h);
    cudaGetSymbolAddress((void**)&p_wq, g_wq);
    cudaGetSymbolAddress((void**)&p_wfc1, g_wfc1);
    cudaGetSymbolAddress((void**)&p_wfc2, g_wfc2);
    cudaGetSymbolAddress((void**)&p_wout, g_wout);
    cudaGetSymbolAddress((void**)&p_wout2, g_wout2);
    cudaGetSymbolAddress((void**)&p_wEFh, g_wEFh);
    cudaGetSymbolAddress((void**)&p_kvpart, g_kvpart);
    cudaGetSymbolAddress((void**)&p_capart, g_capart);

    // opt into >48KB dynamic smem + max shared carveout (2 blocks/SM)
    constexpr int S_FT = gemm_smem<false, true>();   // 61440
    constexpr int S_FF = gemm_smem<false, false>();  // 56832
    constexpr int S_TT = gemm_smem<true, true>();    // 56832
    auto setup = [](const void* f, int smem) {
        cudaFuncSetAttribute(f, cudaFuncAttributeMaxDynamicSharedMemorySize, smem);
        cudaFuncSetAttribute(f, cudaFuncAttributePreferredSharedMemoryCarveout, 100);
    };
    setup((const void*)gemmH<false, true, 1, EpiQT>,  S_FT);
    setup((const void*)gemmH<false, true, 4, EpiKVP>, S_FT);
    setup((const void*)gemmH<false, true, 4, EpiCAP>, S_FT);
    setup((const void*)gemmH<false, false, 1, EpiH>,  S_FF);
    setup((const void*)gemmH<false, true, 1, EpiH>,   S_FT);
    setup((const void*)gemmH<true, true, 1, EpiOut>,  S_TT);
    setup((const void*)gemmH<false, true, 1, EpiOut>, S_FT);

    // ---- streams/events for fork/join inside the capture ----
    cudaStream_t s0 = 0;
    cudaStream_t sA, sB, sC;
    cudaStreamCreateWithFlags(&sA, cudaStreamNonBlocking);
    cudaStreamCreateWithFlags(&sB, cudaStreamNonBlocking);
    cudaStreamCreateWithFlags(&sC, cudaStreamNonBlocking);
    cudaEvent_t evRoot, evNorm, evFc2, evA, evC;
    cudaEventCreateWithFlags(&evRoot, cudaEventDisableTiming);
    cudaEventCreateWithFlags(&evNorm, cudaEventDisableTiming);
    cudaEventCreateWithFlags(&evFc2, cudaEventDisableTiming);
    cudaEventCreateWithFlags(&evA, cudaEventDisableTiming);
    cudaEventCreateWithFlags(&evC, cudaEventDisableTiming);

    // ---- shared prologue on main stream
    cvt_weights<<<3328, 256, 0, s0>>>(qkvv_w, fc1_w, fc2_w, out_w, out2_w);
    pad_wEF<<<256, 256, 0, s0>>>(E_w, F_w);
    pack_xf<<<16384, 128, 0, s0>>>(x);

    cudaEventRecord(evRoot, s0);
    cudaStreamWaitEvent(sA, evRoot, 0);
    cudaStreamWaitEvent(sB, evRoot, 0);

    // ======== branch A (stream sA): dual attention ========
    {
        EpiQT e{p_qkvvTh};
        gemmH<false, true, 1, EpiQT><<<dim3(8, 16, 16), 256, S_FT, sA>>>(
            p_wq, p_xfh, 2048, 1024, 512, 512, 512, 0, 524288, e);
    }
    {
        EpiKVP e{p_kvpart};
        gemmH<false, true, 4, EpiKVP><<<dim3(1, 64, 8), 256, S_FT, sA>>>(
            p_qkvvTh + 8388608, p_wEFh, 8192, 128, 256,
            1024, 1024, 2L * 8388608, 131072, e);
    }
    norm_scale<<<16384, 256, 0, sA>>>();
    cudaEventRecord(evNorm, sA);

    // channel-attn chain continues on sA
    {
        EpiCAP e{p_capart};
        gemmH<false, true, 4, EpiCAP><<<dim3(1, 1, 256), 256, S_FT, sA>>>(
            p_qkvvTh, p_qkvvTh + 8388608, 128, 128, 256, 1024, 1024, 131072, 131072, e);
    }
    softmax_ca<<<8192, 128, 0, sA>>>(temp);
    {
        EpiH e{p_xcah, 131072, 1024, nullptr};
        gemmH<false, false, 1, EpiH><<<dim3(8, 1, 64), 256, S_FF, sA>>>(
            p_attncah, p_qkvvTh + 2L * 8388608, 128, 1024, 128, 128, 1024, 16384, 131072, e);
    }

    // ======== branch C (stream sC): spatial attention, concurrent with ca chain ====
    cudaStreamWaitEvent(sC, evNorm, 0);
    spatial_attn<<<dim3(8, 64), 128, 0, sC>>>(temp2, E_b, F_b);

    // ======== branch B (stream sB): LFE conv-MLP ========
    {
        EpiH e{p_t1h, 2097152, 1024, fc1_b};
        gemmH<false, true, 1, EpiH><<<dim3(8, 16, 16), 256, S_FT, sB>>>(
            p_wfc1, p_xfh, 2048, 1024, 512, 512, 512, 0, 524288, e);
    }
    dwconv_gelu<<<32768, 256, 0, sB>>>(dw_w, dw_b);
    {
        EpiOut e{dout, fc2_b, 0, 0};   // assign: must precede the += epilogues
        gemmH<true, true, 1, EpiOut><<<dim3(4, 8, 16), 256, S_TT, sB>>>(
            p_t2h, p_wfc2, 1024, 512, 2048, 1024, 2048, 2097152, 0, e);
    }
    cudaEventRecord(evFc2, sB);

    // ---- out-projections: disjoint d_out column ranges, run concurrently ----
    // spatial projection (cols 0..255) on sC, after fc2's assign
    cudaStreamWaitEvent(sC, evFc2, 0);
    {
        EpiOut e{dout, out_b, 0, 1};
        gemmH<false, true, 1, EpiOut><<<dim3(2, 8, 16), 256, S_FT, sC>>>(
            p_xsah, p_wout, 1024, 256, 512, 512, 512, 524288, 0, e);
    }
    cudaEventRecord(evC, sC);

    // channel projection (cols 256..511) on sA, after fc2's assign
    cudaStreamWaitEvent(sA, evFc2, 0);
    {
        EpiOut e{dout, out2_b, 256, 1};
        gemmH<true, true, 1, EpiOut><<<dim3(2, 8, 16), 256, S_TT, sA>>>(
            p_xcah, p_wout2, 1024, 256, 512, 1024, 512, 524288, 0, e);
    }
    cudaEventRecord(evA, sA);

    // ---- join all branches back into the main stream
    cudaStreamWaitEvent(s0, evA, 0);
    cudaStreamWaitEvent(s0, evC, 0);

    cudaEventDestroy(evRoot);
    cudaEventDestroy(evNorm);
    cudaEventDestroy(evFc2);
    cudaEventDestroy(evA);
    cudaEventDestroy(evC);
    cudaStreamDestroy(sA);
    cudaStreamDestroy(sB);
    cudaStreamDestroy(sC);
}

// round 16
// speedup vs baseline: 1.5488x; 1.4389x over previous
#include <cuda_runtime.h>
#include <cuda_fp16.h>
#include <math.h>

// Problem constants
// B=16, W=H=32, C=512, HEADS=4, DH=128, N=1024, P=16, HID=2048

// ---------------- scratch (device globals; no allocation allowed) -------------
__device__ half  g_xfh[16384 * 512];         // xf[bn][c]
__device__ half  g_qkvvTh[4 * 8192 * 1024];  // [m][b*4+h][d][n]
__device__ float g_kvpart[8 * 8192 * 16];    // [src*4+ks][bz*128+d][p]
__device__ half  g_attncah[64 * 128 * 128];  // [bz][d][e]
__device__ float g_capart[256 * 128 * 128];  // [bz*4+ks][d][e]
__device__ half  g_xcah[16 * 512 * 1024];    // [b][h*128+d][n]
__device__ half  g_xsah[16 * 512 * 1024];    // [b][n'*512+c'] flat
__device__ half  g_t1h[16 * 2048 * 1024];    // [b][o][n]
__device__ half  g_t2h[16 * 2048 * 1024];    // [b][o][n]
// fp16 weight copies
__device__ half  g_wq[2048 * 512];
__device__ half  g_wfc1[2048 * 512];
__device__ half  g_wfc2[512 * 2048];
__device__ half  g_wout[256 * 512];
__device__ half  g_wout2[256 * 512];
__device__ half  g_wEFh[2 * 128 * 1024];     // [src][p(128, pad)][n]  rows 16..127 = 0

// ---------------- async copy helpers ------------------------------------------
__device__ __forceinline__ void cpa16(unsigned dst, const void* src) {
    asm volatile("cp.async.cg.shared.global [%0], [%1], 16;\n" :: "r"(dst), "l"(src));
}

// ---------------- epilogues (pair interface: j, j+1) ---------------------------
struct EpiH {
    half* C; long csb; int ldc; const float* biasRow;
    __device__ __forceinline__ void operator()(int bz, int i, int j, float v0, float v1) const {
        if (biasRow) { float b = biasRow[i]; v0 += b; v1 += b; }
        *(half2*)&C[(long)bz * csb + (long)i * ldc + j] = __floats2half2_rn(v0, v1);
    }
};
// qkvv direct-to-transposed: i = weight row (0..2047) -> (m,h,d); j = n
struct EpiQT {
    half* out;
    __device__ __forceinline__ void operator()(int b, int i, int j, float v0, float v1) const {
        int m = i >> 9, hh = (i >> 7) & 3, d = i & 127;
        *(half2*)&out[((long)(m * 64 + b * 4 + hh)) * 131072 + (long)d * 1024 + j] =
            __floats2half2_rn(v0, v1);
    }
};
// kv partial: z = src*4+ks, i = bz*128+d, j = p (<16 valid), fp32 partial
struct EpiKVP {
    float* part;   // [8][8192][16]
    __device__ __forceinline__ void operator()(int z, int i, int j, float v0, float v1) const {
        if (j >= 16) return;
        long idx = ((long)z * 8192 + i) * 16 + j;
        part[idx] = v0; part[idx + 1] = v1;
    }
};
// channel-attn partial: z = bz*4+ks, fp32 partial [256][128][128]
struct EpiCAP {
    float* part;
    __device__ __forceinline__ void operator()(int z, int i, int j, float v0, float v1) const {
        long idx = ((long)z * 128 + i) * 128 + j;
        part[idx] = v0; part[idx + 1] = v1;
    }
};
// final d_out (B,W,H,C) fp32, n -> (h=n>>5, w=n&31), col offset, opt accumulate
struct EpiOut {
    float* out; const float* bias; int coff; int accum;
    __device__ __forceinline__ void operator()(int b, int n, int j, float v0, float v1) const {
        v0 += bias[j]; v1 += bias[j + 1];
        int h = n >> 5, w = n & 31;
        long idx = (((long)(b * 32 + w)) * 32 + h) * 512 + coff + j;
        if (accum) { out[idx] += v0; out[idx + 1] += v1; }
        else       { out[idx] = v0;  out[idx + 1] = v1; }
    }
};

// ---------------- FP16 GEMM: 3-stage cp.async ring, 1 sync/K-step --------------
// C[i][j] = sum_k A(i,k)*B(j,k), fp32 accumulate.
// AT=false: A (M,K) k-contiguous -> smem [m][k] pitch 40, ldmatrix
// AT=true : A (K,M) m-contiguous -> smem [k][m] pitch 136, ldmatrix.trans
// BT analogous. KSPLIT: blockIdx.z = bz*KSPLIT + ks; K = split length.
template<bool AT, bool BT, int KSPLIT, class Epi>
__global__ void __launch_bounds__(256, 2) gemmH(
    const half* __restrict__ A, const half* __restrict__ B,
    int M, int N, int K, int lda, int ldb, long asb, long bsb, Epi epi)
{
    constexpr int ATILE = AT ? 32 * 136 : 128 * 40;   // halves per stage
    constexpr int BTILE = BT ? 128 * 40 : 32 * 136;
    extern __shared__ __align__(16) half sm[];

    int z = blockIdx.z;
    int bz = z / KSPLIT, ks = z % KSPLIT;
    const half* Ab = A + (long)bz * asb + (AT ? (long)ks * K * lda : (long)ks * K);
    const half* Bb = B + (long)bz * bsb + (BT ? (long)ks * K : (long)ks * K * ldb);
    int bm = blockIdx.y * 128, bn = blockIdx.x * 128;
    int tid = threadIdx.x, lane = tid & 31, warp = tid >> 5;
    int wm = (warp >> 2) * 64, wn = (warp & 3) * 32;
    int g = lane >> 2, t = lane & 3;

    unsigned AsU = (unsigned)__cvta_generic_to_shared(sm);
    unsigned BsU = (unsigned)__cvta_generic_to_shared(sm + 3 * ATILE);

    float c[4][4][4];
#pragma unroll
    for (int mt = 0; mt < 4; mt++)
#pragma unroll
        for (int nt = 0; nt < 4; nt++)
#pragma unroll
            for (int r = 0; r < 4; r++) c[mt][nt][r] = 0.f;

    auto issue = [&](int stage, int k0) {
#pragma unroll
        for (int i = 0; i < 2; i++) {
            int item = tid + i * 256;
            if (!AT) {
                int row = item >> 2, cc = item & 3;
                cpa16(AsU + (stage * ATILE + row * 40 + cc * 8) * 2,
                      Ab + (long)(bm + row) * lda + k0 + cc * 8);
            } else {
                int k = item >> 4, cc = item & 15;
                cpa16(AsU + (stage * ATILE + k * 136 + cc * 8) * 2,
                      Ab + (long)(k0 + k) * lda + bm + cc * 8);
            }
        }
#pragma unroll
        for (int i = 0; i < 2; i++) {
            int item = tid + i * 256;
            if (BT) {
                int row = item >> 2, cc = item & 3;
                cpa16(BsU + (stage * BTILE + row * 40 + cc * 8) * 2,
                      Bb + (long)(bn + row) * ldb + k0 + cc * 8);
            } else {
                int k = item >> 4, cc = item & 15;
                cpa16(BsU + (stage * BTILE + k * 136 + cc * 8) * 2,
                      Bb + (long)(k0 + k) * ldb + bn + cc * 8);
            }
        }
        asm volatile("cp.async.commit_group;\n" ::: "memory");
    };

    issue(0, 0);
    issue(1, 32);
    int nsteps = K >> 5;

    for (int si = 0; si < nsteps; si++) {
        int stage = si % 3;
        int kn = (si + 2) * 32;
        if (kn < K) {
            asm volatile("cp.async.wait_group 1;\n" ::: "memory");
        } else {
            asm volatile("cp.async.wait_group 0;\n" ::: "memory");
        }
        __syncthreads();
        if (kn < K) issue((si + 2) % 3, kn);

        unsigned abase = AsU + stage * ATILE * 2;
        unsigned bbase = BsU + stage * BTILE * 2;

#pragma unroll
        for (int kc = 0; kc < 2; kc++) {
            int kb = kc * 16;
            unsigned af[4][4], bf[4][2];
            if (!AT) {
#pragma unroll
                for (int mt = 0; mt < 4; mt++) {
                    int row = wm + mt * 16 + (lane & 15);
                    int kof = kb + ((lane >> 4) << 3);
                    unsigned addr = abase + (row * 40 + kof) * 2;
                    asm volatile(
                        "ldmatrix.sync.aligned.m8n8.x4.shared.b16 {%0,%1,%2,%3}, [%4];"
                        : "=r"(af[mt][0]), "=r"(af[mt][1]), "=r"(af[mt][2]), "=r"(af[mt][3])
                        : "r"(addr));
                }
            } else {
#pragma unroll
                for (int mt = 0; mt < 4; mt++) {
                    int row_k = kb + ((lane >> 4) & 1) * 8 + (lane & 7);
                    int col_m = wm + mt * 16 + ((lane >> 3) & 1) * 8;
                    unsigned addr = abase + (row_k * 136 + col_m) * 2;
                    asm volatile(
                        "ldmatrix.sync.aligned.m8n8.x4.trans.shared.b16 {%0,%1,%2,%3}, [%4];"
                        : "=r"(af[mt][0]), "=r"(af[mt][1]), "=r"(af[mt][2]), "=r"(af[mt][3])
                        : "r"(addr));
                }
            }
            if (BT) {
#pragma unroll
                for (int p = 0; p < 2; p++) {
                    int nt = 2 * p + (lane >> 4);
                    int row = wn + nt * 8 + (lane & 7);
                    int kof = kb + (((lane >> 3) & 1) << 3);
                    unsigned addr = bbase + (row * 40 + kof) * 2;
                    asm volatile(
                        "ldmatrix.sync.aligned.m8n8.x4.shared.b16 {%0,%1,%2,%3}, [%4];"
                        : "=r"(bf[2 * p][0]), "=r"(bf[2 * p][1]),
                          "=r"(bf[2 * p + 1][0]), "=r"(bf[2 * p + 1][1])
                        : "r"(addr));
                }
            } else {
#pragma unroll
                for (int p = 0; p < 2; p++) {
                    int row_k = kb + ((lane >> 3) & 1) * 8 + (lane & 7);
                    int col_n = wn + (2 * p + (lane >> 4)) * 8;
                    unsigned addr = bbase + (row_k * 136 + col_n) * 2;
                    asm volatile(
                        "ldmatrix.sync.aligned.m8n8.x4.trans.shared.b16 {%0,%1,%2,%3}, [%4];"
                        : "=r"(bf[2 * p][0]), "=r"(bf[2 * p][1]),
                          "=r"(bf[2 * p + 1][0]), "=r"(bf[2 * p + 1][1])
                        : "r"(addr));
                }
            }
#pragma unroll
            for (int mt = 0; mt < 4; mt++)
#pragma unroll
                for (int nt = 0; nt < 4; nt++) {
                    asm volatile(
                        "mma.sync.aligned.m16n8k16.row.col.f32.f16.f16.f32 "
                        "{%0,%1,%2,%3},{%4,%5,%6,%7},{%8,%9},{%0,%1,%2,%3};\n"
                        : "+f"(c[mt][nt][0]), "+f"(c[mt][nt][1]),
                          "+f"(c[mt][nt][2]), "+f"(c[mt][nt][3])
                        : "r"(af[mt][0]), "r"(af[mt][1]), "r"(af[mt][2]), "r"(af[mt][3]),
                          "r"(bf[nt][0]), "r"(bf[nt][1]));
                }
        }
    }

#pragma unroll
    for (int mt = 0; mt < 4; mt++)
#pragma unroll
        for (int nt = 0; nt < 4; nt++) {
            int i = wm + mt * 16 + g;
            int j = wn + nt * 8 + t * 2;
            epi(z, bm + i,     bn + j, c[mt][nt][0], c[mt][nt][1]);
            epi(z, bm + i + 8, bn + j, c[mt][nt][2], c[mt][nt][3]);
        }
}

// smem bytes per instantiation
template<bool AT, bool BT>
constexpr int gemm_smem() {
    return ((AT ? 32 * 136 : 128 * 40) + (BT ? 128 * 40 : 32 * 136)) * 3 * 2;
}

// ---------------- merged prologue: weights cvt + E/F pad + x pack --------------
// blocks [0,3328): cvt (851968 float4 units); [3328,3584): pad (65536 units);
// [3584,11776): pack (8192 blocks, 2 rows each). 256 threads.
__global__ void prologue(const float* __restrict__ qw, const float* __restrict__ f1,
                         const float* __restrict__ f2, const float* __restrict__ ow,
                         const float* __restrict__ o2, const float* __restrict__ E_w,
                         const float* __restrict__ F_w, const float* __restrict__ x) {
    int blk = blockIdx.x;
    if (blk < 3328) {
        long i4 = (long)blk * 256 + threadIdx.x;   // < 851968
        const float* src; half* dst; long off;
        if (i4 < 262144)      { src = qw; dst = g_wq;   off = i4; }
        else if (i4 < 524288) { src = f1; dst = g_wfc1; off = i4 - 262144; }
        else if (i4 < 786432) { src = f2; dst = g_wfc2; off = i4 - 524288; }
        else if (i4 < 819200) { src = ow; dst = g_wout; off = i4 - 786432; }
        else                  { src = o2; dst = g_wout2; off = i4 - 819200; }
        float4 v = *(const float4*)(src + off * 4);
        half2 h0 = __floats2half2_rn(v.x, v.y), h1 = __floats2half2_rn(v.z, v.w);
        uint2 u; u.x = *(unsigned*)&h0; u.y = *(unsigned*)&h1;
        *(uint2*)(dst + off * 4) = u;
    } else if (blk < 3584) {
        long i4 = (long)(blk - 3328) * 256 + threadIdx.x;   // < 65536
        int z = (int)(i4 >> 15);
        long rem = i4 & 32767;
        int p = (int)(rem >> 8);
        int n4 = (int)(rem & 255);
        half2 h0, h1;
        if (p < 16) {
            const float* w = (z ? F_w : E_w) + (long)p * 1024 + n4 * 4;
            float4 v = *(const float4*)w;
            h0 = __floats2half2_rn(v.x, v.y); h1 = __floats2half2_rn(v.z, v.w);
        } else {
            h0 = __floats2half2_rn(0.f, 0.f); h1 = h0;
        }
        uint2 u; u.x = *(unsigned*)&h0; u.y = *(unsigned*)&h1;
        *(uint2*)(g_wEFh + i4 * 4) = u;
    } else {
        int r2 = (blk - 3584) * 2 + (threadIdx.x >> 7);   // dst row = b*1024 + n
        int t = threadIdx.x & 127;
        int b = r2 >> 10, n = r2 & 1023;
        int h = n >> 5, w = n & 31;
        const float* src = x + (((long)(b * 32 + w)) * 32 + h) * 512;
        half* dst = g_xfh + (long)r2 * 512;
        float4 v = *(const float4*)&src[t * 4];
        half2 h0 = __floats2half2_rn(v.x, v.y), h1 = __floats2half2_rn(v.z, v.w);
        uint2 u; u.x = *(unsigned*)&h0; u.y = *(unsigned*)&h1;
        *(uint2*)&dst[t * 4] = u;
    }
}

// ---------------- L2-normalize q and k rows (fp16 in place, fp32 math) ---------
__global__ void norm_scale() {
    half* row = g_qkvvTh + (long)blockIdx.x * 1024;   // rows 0..16383 = m0,m1
    int t = threadIdx.x; // 256
    half2 h[2];
    *(uint2*)h = *(const uint2*)(row + t * 4);
    float2 a = __half22float2(h[0]), b = __half22float2(h[1]);
    float s = a.x*a.x + a.y*a.y + b.x*b.x + b.y*b.y;
    __shared__ float sd[256];
    sd[t] = s; __syncthreads();
    for (int o = 128; o > 0; o >>= 1) { if (t < o) sd[t] += sd[t + o]; __syncthreads(); }
    float inv = 1.0f / fmaxf(sqrtf(sd[0]), 1e-12f);
    h[0] = __floats2half2_rn(a.x * inv, a.y * inv);
    h[1] = __floats2half2_rn(b.x * inv, b.y * inv);
    *(uint2*)(row + t * 4) = *(uint2*)h;
}

// ---------------- softmax over e (128): sums 4 K-split partials ----------------
__global__ void softmax_ca(const float* __restrict__ temp) {
    int r = blockIdx.x;           // bz*128 + d
    int bz = r >> 7;
    int h = (bz & 3);
    float tv = temp[h];
    int t = threadIdx.x; // 128
    long base = ((long)(bz * 4) * 128 + (r & 127)) * 128 + t;
    float v = g_capart[base] + g_capart[base + 16384] + g_capart[base + 32768] + g_capart[base + 49152];
    v *= tv;
    __shared__ float sd[128];
    sd[t] = v; __syncthreads();
    for (int o = 64; o > 0; o >>= 1) { if (t < o) sd[t] = fmaxf(sd[t], sd[t + o]); __syncthreads(); }
    float mx = sd[0]; __syncthreads();
    float e = expf(v - mx);
    sd[t] = e; __syncthreads();
    for (int o = 64; o > 0; o >>= 1) { if (t < o) sd[t] += sd[t + o]; __syncthreads(); }
    g_attncah[(long)r * 128 + t] = __float2half(e / sd[0]);
}

// ---------------- fused projected spatial attention (sums kv partials) ---------
__global__ void spatial_attn(const float* __restrict__ temp2,
                             const float* __restrict__ E_b, const float* __restrict__ F_b) {
    int bz = blockIdx.y; int b = bz >> 2, h = bz & 3;
    int n = blockIdx.x * 128 + threadIdx.x;
    __shared__ float kps[128][16];
    __shared__ float vps[128][16];
    for (int i = threadIdx.x; i < 2048; i += 128) {
        int d = i >> 4, p = i & 15;
        long base = ((long)(bz * 128 + d)) * 16 + p;
        float kv = E_b[p], vv = F_b[p];
#pragma unroll
        for (int s = 0; s < 4; s++) {
            kv += g_kvpart[(long)s * 131072 + base];
            vv += g_kvpart[(long)(4 + s) * 131072 + base];
        }
        kps[d][p] = kv; vps[d][p] = vv;
    }
    __syncthreads();
    const half* q = g_qkvvTh + (long)bz * 131072 + n; // m=0 (normalized q)
    float lg[16];
#pragma unroll
    for (int p = 0; p < 16; p++) lg[p] = 0.f;
    for (int d = 0; d < 128; d++) {
        float qv = __half2float(q[(long)d * 1024]);
#pragma unroll
        for (int p = 0; p < 16; p++) lg[p] += qv * kps[d][p];
    }
    float tv = temp2[h];
    float mx = -1e30f;
#pragma unroll
    for (int p = 0; p < 16; p++) { lg[p] *= tv; mx = fmaxf(mx, lg[p]); }
    float s = 0.f;
#pragma unroll
    for (int p = 0; p < 16; p++) { lg[p] = expf(lg[p] - mx); s += lg[p]; }
    float inv = 1.0f / s;
#pragma unroll
    for (int p = 0; p < 16; p++) lg[p] *= inv;
    half* ob = g_xsah + (long)b * 524288 + h * 1024 + n;
    for (int cc = 0; cc < 128; cc += 8) {
        float acc[8];
#pragma unroll
        for (int dd = 0; dd < 8; dd++) acc[dd] = 0.f;
#pragma unroll
        for (int p = 0; p < 16; p++) {
            float ap = lg[p];
#pragma unroll
            for (int dd = 0; dd < 8; dd++) acc[dd] += ap * vps[cc + dd][p];
        }
#pragma unroll
        for (int dd = 0; dd < 8; dd++) ob[(long)(cc + dd) * 4096] = __float2half(acc[dd]);
    }
}

// ---------------- depthwise 3x3 (SAME) + exact GELU, fp16 io --------------------
__global__ void dwconv_gelu(const float* __restrict__ w, const float* __restrict__ bias) {
    long bo = blockIdx.x;                 // b*2048 + o
    int och = (int)(bo & 2047);
    const half* img = g_t1h + bo * 1024;
    __shared__ float s[1024];
    int tid = threadIdx.x; // 256
    {
        uint2 u = *(const uint2*)&img[tid * 4];
        float2 a = __half22float2(*(half2*)&u.x), b2 = __half22float2(*(half2*)&u.y);
        s[tid * 4] = a.x; s[tid * 4 + 1] = a.y; s[tid * 4 + 2] = b2.x; s[tid * 4 + 3] = b2.y;
    }
    float wv[9];
#pragma unroll
    for (int k = 0; k < 9; k++) wv[k] = w[och * 9 + k];
    float bb = bias[och];
    __syncthreads();
    half* ob = g_t2h + bo * 1024;
    for (int p = tid; p < 1024; p += 256) {
        int h = p >> 5, ww = p & 31;
        float acc = bb;
#pragma unroll
        for (int i = 0; i < 3; i++) {
            int hh = h + i - 1;
            if (hh < 0 || hh > 31) continue;
#pragma unroll
            for (int j = 0; j < 3; j++) {
                int w2 = ww + j - 1;
                if (w2 < 0 || w2 > 31) continue;
                acc += s[hh * 32 + w2] * wv[i * 3 + j];
            }
        }
        ob[p] = __float2half(0.5f * acc * (1.0f + erff(acc * 0.70710678118654752440f)));
    }
}

// ---------------- launch ------------------------------------------------------
extern "C" void kernel_launch(void* const* d_in, const int* in_sizes, int n_in,
                              void* d_out_v, int out_size) {
    const float* x      = (const float*)d_in[0];
    const float* qkvv_w = (const float*)d_in[1];
    const float* E_w    = (const float*)d_in[2];
    const float* E_b    = (const float*)d_in[3];
    const float* F_w    = (const float*)d_in[4];
    const float* F_b    = (const float*)d_in[5];
    const float* temp   = (const float*)d_in[6];
    const float* temp2  = (const float*)d_in[7];
    const float* out_w  = (const float*)d_in[8];
    const float* out_b  = (const float*)d_in[9];
    const float* out2_w = (const float*)d_in[10];
    const float* out2_b = (const float*)d_in[11];
    const float* fc1_w  = (const float*)d_in[12];
    const float* fc1_b  = (const float*)d_in[13];
    const float* dw_w   = (const float*)d_in[14];
    const float* dw_b   = (const float*)d_in[15];
    const float* fc2_w  = (const float*)d_in[16];
    const float* fc2_b  = (const float*)d_in[17];
    float* dout = (float*)d_out_v;

    half *p_xfh, *p_qkvvTh, *p_attncah, *p_xcah, *p_xsah, *p_t1h, *p_t2h;
    half *p_wq, *p_wfc1, *p_wfc2, *p_wout, *p_wout2, *p_wEFh;
    float *p_kvpart, *p_capart;
    cudaGetSymbolAddress((void**)&p_xfh, g_xfh);
    cudaGetSymbolAddress((void**)&p_qkvvTh, g_qkvvTh);
    cudaGetSymbolAddress((void**)&p_attncah, g_attncah);
    cudaGetSymbolAddress((void**)&p_xcah, g_xcah);
    cudaGetSymbolAddress((void**)&p_xsah, g_xsah);
    cudaGetSymbolAddress((void**)&p_t1h, g_t1h);
    cudaGetSymbolAddress((void**)&p_t2h, g_t2h);
    cudaGetSymbolAddress((void**)&p_wq, g_wq);
    cudaGetSymbolAddress((void**)&p_wfc1, g_wfc1);
    cudaGetSymbolAddress((void**)&p_wfc2, g_wfc2);
    cudaGetSymbolAddress((void**)&p_wout, g_wout);
    cudaGetSymbolAddress((void**)&p_wout2, g_wout2);
    cudaGetSymbolAddress((void**)&p_wEFh, g_wEFh);
    cudaGetSymbolAddress((void**)&p_kvpart, g_kvpart);
    cudaGetSymbolAddress((void**)&p_capart, g_capart);

    // opt into >48KB dynamic smem + max shared carveout (2 blocks/SM)
    constexpr int S_FT = gemm_smem<false, true>();   // 61440
    constexpr int S_FF = gemm_smem<false, false>();  // 56832
    constexpr int S_TT = gemm_smem<true, true>();    // 56832
    auto setup = [](const void* f, int smem) {
        cudaFuncSetAttribute(f, cudaFuncAttributeMaxDynamicSharedMemorySize, smem);
        cudaFuncSetAttribute(f, cudaFuncAttributePreferredSharedMemoryCarveout, 100);
    };
    setup((const void*)gemmH<false, true, 1, EpiQT>,  S_FT);
    setup((const void*)gemmH<false, true, 4, EpiKVP>, S_FT);
    setup((const void*)gemmH<false, true, 4, EpiCAP>, S_FT);
    setup((const void*)gemmH<false, false, 1, EpiH>,  S_FF);
    setup((const void*)gemmH<false, true, 1, EpiH>,   S_FT);
    setup((const void*)gemmH<true, true, 1, EpiOut>,  S_TT);
    setup((const void*)gemmH<false, true, 1, EpiOut>, S_FT);

    // ---- fork/join streams inside the capture (R13 topology) ----
    cudaStream_t s0 = 0;
    cudaStream_t sA, sB;
    cudaStreamCreateWithFlags(&sA, cudaStreamNonBlocking);
    cudaStreamCreateWithFlags(&sB, cudaStreamNonBlocking);
    cudaEvent_t evRoot, evA, evB;
    cudaEventCreateWithFlags(&evRoot, cudaEventDisableTiming);
    cudaEventCreateWithFlags(&evA, cudaEventDisableTiming);
    cudaEventCreateWithFlags(&evB, cudaEventDisableTiming);

    // ---- merged prologue on main stream
    prologue<<<11776, 256, 0, s0>>>(qkvv_w, fc1_w, fc2_w, out_w, out2_w, E_w, F_w, x);

    cudaEventRecord(evRoot, s0);
    cudaStreamWaitEvent(sA, evRoot, 0);
    cudaStreamWaitEvent(sB, evRoot, 0);

    // ======== branch A (stream sA): dual attention ========
    {
        EpiQT e{p_qkvvTh};
        gemmH<false, true, 1, EpiQT><<<dim3(8, 16, 16), 256, S_FT, sA>>>(
            p_wq, p_xfh, 2048, 1024, 512, 512, 512, 0, 524288, e);
    }
    {
        EpiKVP e{p_kvpart};
        gemmH<false, true, 4, EpiKVP><<<dim3(1, 64, 8), 256, S_FT, sA>>>(
            p_qkvvTh + 8388608, p_wEFh, 8192, 128, 256,
            1024, 1024, 2L * 8388608, 131072, e);
    }
    norm_scale<<<16384, 256, 0, sA>>>();
    {
        EpiCAP e{p_capart};
        gemmH<false, true, 4, EpiCAP><<<dim3(1, 1, 256), 256, S_FT, sA>>>(
            p_qkvvTh, p_qkvvTh + 8388608, 128, 128, 256, 1024, 1024, 131072, 131072, e);
    }
    softmax_ca<<<8192, 128, 0, sA>>>(temp);
    {
        EpiH e{p_xcah, 131072, 1024, nullptr};
        gemmH<false, false, 1, EpiH><<<dim3(8, 1, 64), 256, S_FF, sA>>>(
            p_attncah, p_qkvvTh + 2L * 8388608, 128, 1024, 128, 128, 1024, 16384, 131072, e);
    }
    spatial_attn<<<dim3(8, 64), 128, 0, sA>>>(temp2, E_b, F_b);

    // ======== branch B (stream sB): LFE conv-MLP ========
    {
        EpiH e{p_t1h, 2097152, 1024, fc1_b};
        gemmH<false, true, 1, EpiH><<<dim3(8, 16, 16), 256, S_FT, sB>>>(
            p_wfc1, p_xfh, 2048, 1024, 512, 512, 512, 0, 524288, e);
    }
    dwconv_gelu<<<32768, 256, 0, sB>>>(dw_w, dw_b);
    {
        EpiOut e{dout, fc2_b, 0, 0};   // assign: must precede the += epilogues
        gemmH<true, true, 1, EpiOut><<<dim3(4, 8, 16), 256, S_TT, sB>>>(
            p_t2h, p_wfc2, 1024, 512, 2048, 1024, 2048, 2097152, 0, e);
    }

    // ---- join both branches back into the main stream
    cudaEventRecord(evA, sA);
    cudaEventRecord(evB, sB);
    cudaStreamWaitEvent(s0, evA, 0);
    cudaStreamWaitEvent(s0, evB, 0);

    // ---- epilogue on main stream: accumulate projections into d_out
    {
        EpiOut e{dout, out_b, 0, 1};
        gemmH<false, true, 1, EpiOut><<<dim3(2, 8, 16), 256, S_FT, s0>>>(
            p_xsah, p_wout, 1024, 256, 512, 512, 512, 524288, 0, e);
    }
    {
        EpiOut e{dout, out2_b, 256, 1};
        gemmH<true, true, 1, EpiOut><<<dim3(2, 8, 16), 256, S_TT, s0>>>(
            p_xcah, p_wout2, 1024, 256, 512, 1024, 512, 524288, 0, e);
    }

    cudaEventDestroy(evRoot);
    cudaEventDestroy(evA);
    cudaEventDestroy(evB);
    cudaStreamDestroy(sA);
    cudaStreamDestroy(sB);
}